// round 17
// baseline (speedup 1.0000x reference)
#include <cuda_runtime.h>
#include <cstdint>

namespace {

constexpr int Bz  = 4;
constexpr int NHn = 4;
constexpr int Tn  = 512;
constexpr int Dn  = 256;
constexpr int Nn  = 8192;
constexpr int BHn = Bz * NHn;
constexpr float SCALEF = 0.011048543456039806f;  // N^-0.5

// Scratch (device globals; allocation-free). All values tf32-pre-rounded fp32.
// The k-contiguous (contraction) index of every tensor is stored PERMUTED by
// perm8: within each group of 8, k -> 2*(k&3) | ((k>>2)&1). Both operands of
// every GEMM carry the same permutation, so contraction pairing is unchanged;
// it exists purely so (tig, tig+4) fragment pairs are SMEM-adjacent (LDS.64).
__device__ float g_qr[(size_t)BHn * Tn * Nn];   // RoPE(Q)    (t, pi(n))
__device__ float g_qt[(size_t)BHn * Nn * Tn];   // RoPE(Q)^T  (n, pi(t))
__device__ float g_st[(size_t)BHn * Dn * Nn];   // state^T    (d, pi(n))
__device__ float g_vt[(size_t)Bz * Dn * Tn];    // V^T        (d, pi(t))
__device__ float g_sc[(size_t)BHn * Tn * Tn];   // masked scores (t, pi(s))
__device__ float g_oa[(size_t)BHn * Tn * Dn];   // partial out: QR @ state (plain)

__device__ __forceinline__ int perm8(int k) {
    return (k & ~7) | (((k & 3) << 1) | ((k >> 2) & 1));
}

// ---------------------------------------------------------------------------
// Tiling: CTA tile 128(m) x 256(n), BK=32. 8 warps as 2(m) x 4(n);
// warp tile 64x64. SMEM rows [36 words]; A [128][36], B [256][36].
// 3-stage cp.async pipeline, 1 CTA/SM. Fragments load via LDS.64.
// ---------------------------------------------------------------------------
constexpr int BM = 128, BN = 256, BK = 32;
constexpr int RSTR = 36;
constexpr int A_WORDS = BM * RSTR;               // 4608
constexpr int B_WORDS = BN * RSTR;               // 9216
constexpr int STAGE_WORDS = A_WORDS + B_WORDS;   // 13824
constexpr int STG = 3;
constexpr int SMEM_TOTAL = STG * STAGE_WORDS * 4;  // 165888 B
constexpr int NT = 256;

__device__ __forceinline__ uint32_t f2t(float x) {
    uint32_t u;
    asm("cvt.rna.tf32.f32 %0, %1;" : "=r"(u) : "f"(x));
    return u;
}
__device__ __forceinline__ float f2tf(float x) { return __uint_as_float(f2t(x)); }

__device__ __forceinline__ uint32_t smem_u32(const void* p) {
    uint32_t a;
    asm("{ .reg .u64 t; cvta.to.shared.u64 t, %1; cvt.u32.u64 %0, t; }"
        : "=r"(a) : "l"(p));
    return a;
}

__device__ __forceinline__ void mma_tf32(float c[4], const uint32_t a[4],
                                         const uint32_t b[2]) {
    asm volatile(
        "mma.sync.aligned.m16n8k8.row.col.f32.tf32.tf32.f32 "
        "{%0,%1,%2,%3}, {%4,%5,%6,%7}, {%8,%9}, {%0,%1,%2,%3};"
        : "+f"(c[0]), "+f"(c[1]), "+f"(c[2]), "+f"(c[3])
        : "r"(a[0]), "r"(a[1]), "r"(a[2]), "r"(a[3]), "r"(b[0]), "r"(b[1]));
}

// One k-octet of the 64x64 warp tile. k-permuted layout: true k=tig at word
// ko+2*tig, true k=tig+4 at ko+2*tig+1 -> each frag pair is one LDS.64.
__device__ __forceinline__ void mma_oct(const uint32_t* __restrict__ As,
                                        const uint32_t* __restrict__ Bs,
                                        int ko, int wm, int wn,
                                        int gid, int tig, float c[32][4]) {
    const int kc = ko + 2 * tig;
    uint32_t a[4][4], b[8][2];
#pragma unroll
    for (int im = 0; im < 4; ++im) {
        const uint32_t* pa = As + (wm + im * 16 + gid) * RSTR + kc;
        uint2 q0 = *reinterpret_cast<const uint2*>(pa);
        uint2 q1 = *reinterpret_cast<const uint2*>(pa + 8 * RSTR);
        a[im][0] = q0.x; a[im][1] = q1.x; a[im][2] = q0.y; a[im][3] = q1.y;
    }
#pragma unroll
    for (int jn = 0; jn < 8; ++jn) {
        const uint32_t* pb = Bs + (wn + jn * 8 + gid) * RSTR + kc;
        uint2 q = *reinterpret_cast<const uint2*>(pb);
        b[jn][0] = q.x; b[jn][1] = q.y;
    }
#pragma unroll
    for (int im = 0; im < 4; ++im)
#pragma unroll
        for (int jn = 0; jn < 8; ++jn)
            mma_tf32(c[im * 8 + jn], a[im], b[jn]);
}

// cp.async tiles (k contiguous in source, row stride ld). 256 threads.
__device__ __forceinline__ void cp_A(uint32_t dbase,
                                     const float* __restrict__ src, int ld) {
#pragma unroll
    for (int i = 0; i < 4; ++i) {
        int ch = threadIdx.x + i * NT;
        int row = ch >> 3, kc = (ch & 7) * 4;
        uint32_t d = dbase + (uint32_t)((row * RSTR + kc) * 4);
        asm volatile("cp.async.cg.shared.global [%0], [%1], 16;"
                     :: "r"(d), "l"(src + (size_t)row * ld + kc));
    }
}
__device__ __forceinline__ void cp_B(uint32_t dbase,
                                     const float* __restrict__ src, int ld) {
#pragma unroll
    for (int i = 0; i < 8; ++i) {
        int ch = threadIdx.x + i * NT;
        int row = ch >> 3, kc = (ch & 7) * 4;
        uint32_t d = dbase + (uint32_t)((row * RSTR + kc) * 4);
        asm volatile("cp.async.cg.shared.global [%0], [%1], 16;"
                     :: "r"(d), "l"(src + (size_t)row * ld + kc));
    }
}
#define CP_COMMIT() asm volatile("cp.async.commit_group;" ::: "memory")
#define CP_WAIT1()  asm volatile("cp.async.wait_group 1;" ::: "memory")

// ---------------------------------------------------------------------------
// Shared GEMM mainloop. Fetch(kt) -> {A ptr, lda, B ptr, ldb}.
// ---------------------------------------------------------------------------
struct SrcPair { const float* a; int la; const float* b; int lb; };

template <typename F>
__device__ __forceinline__ void gemm_main(uint32_t sb, const uint32_t* smu,
                                          int KT, F fetch_src,
                                          int wm, int wn, int gid, int tig,
                                          float c[32][4]) {
    auto abase = [&](int st) { return sb + (uint32_t)(st * STAGE_WORDS * 4); };
#pragma unroll
    for (int p = 0; p < STG - 1; ++p) {
        if (p < KT) {
            SrcPair s = fetch_src(p);
            cp_A(abase(p), s.a, s.la);
            cp_B(abase(p) + A_WORDS * 4, s.b, s.lb);
        }
        CP_COMMIT();
    }
    int rs = 0;
    for (int kt = 0; kt < KT; ++kt) {
        CP_WAIT1();
        __syncthreads();
        int pf = kt + STG - 1;
        if (pf < KT) {
            int ws = rs + STG - 1;
            if (ws >= STG) ws -= STG;
            SrcPair s = fetch_src(pf);
            cp_A(abase(ws), s.a, s.la);
            cp_B(abase(ws) + A_WORDS * 4, s.b, s.lb);
        }
        CP_COMMIT();
        const uint32_t* As = smu + (size_t)rs * STAGE_WORDS;
        const uint32_t* Bs = As + A_WORDS;
#pragma unroll
        for (int ko = 0; ko < BK; ko += 8)
            mma_oct(As, Bs, ko, wm, wn, gid, tig, c);
        if (++rs == STG) rs = 0;
    }
}

// ---------------------------------------------------------------------------
// Prepasses. Identical values to round 16; the k-contiguous index of each
// output is stored at perm8(idx) (permutes within 32B sectors: coalescing
// unchanged).
// ---------------------------------------------------------------------------
__global__ void rope_kernel(const float* __restrict__ Q,
                            const float* __restrict__ C,
                            const float* __restrict__ S) {
    __shared__ float tile[32][65];
    const int bh = blockIdx.z, t0 = blockIdx.y * 32, n0 = blockIdx.x * 64;
    const int tid = threadIdx.x;
    const size_t qbase = ((size_t)bh * Tn + t0) * Nn + n0;
#pragma unroll
    for (int i = 0; i < 4; ++i) {
        int p  = tid + i * 256;
        int tt = p >> 5, pi = p & 31;
        int nn = pi * 2;
        float2 q = *reinterpret_cast<const float2*>(Q + qbase + (size_t)tt * Nn + nn);
        float2 c = *reinterpret_cast<const float2*>(C + (size_t)(t0 + tt) * Nn + n0 + nn);
        float2 s = *reinterpret_cast<const float2*>(S + (size_t)(t0 + tt) * Nn + n0 + nn);
        float2 r;
        r.x = f2tf(q.x * c.x - q.y * s.x);
        r.y = f2tf(q.y * c.y + q.x * s.y);
        size_t o = qbase + (size_t)tt * Nn;
        g_qr[o + perm8(nn)]     = r.x;
        g_qr[o + perm8(nn + 1)] = r.y;
        tile[tt][nn] = r.x;
        tile[tt][nn + 1] = r.y;
    }
    __syncthreads();
    const size_t tbase = ((size_t)bh * Nn + n0) * Tn + t0;
#pragma unroll
    for (int i = 0; i < 8; ++i) {
        int e  = tid + i * 256;
        int nn = e >> 5, tt = e & 31;
        g_qt[tbase + (size_t)nn * Tn + perm8(tt)] = tile[tt][nn];
    }
}

__global__ void stateT_kernel(const float* __restrict__ St) {
    __shared__ float tile[32][33];
    const int bh = blockIdx.z, n0 = blockIdx.x * 32, d0 = blockIdx.y * 32;
    const int tid = threadIdx.x;
#pragma unroll
    for (int i = 0; i < 4; ++i) {
        int e = tid + i * 256;
        int nn = e >> 5, dd = e & 31;
        tile[nn][dd] = St[((size_t)bh * Nn + n0 + nn) * Dn + d0 + dd];
    }
    __syncthreads();
#pragma unroll
    for (int i = 0; i < 4; ++i) {
        int e = tid + i * 256;
        int dd = e >> 5, nn = e & 31;
        g_st[((size_t)bh * Dn + d0 + dd) * Nn + n0 + perm8(nn)] = f2tf(tile[nn][dd]);
    }
}

__global__ void vT_kernel(const float* __restrict__ V) {
    __shared__ float tile[32][33];
    const int b = blockIdx.z, t0 = blockIdx.x * 32, d0 = blockIdx.y * 32;
    const int tid = threadIdx.x;
#pragma unroll
    for (int i = 0; i < 4; ++i) {
        int e = tid + i * 256;
        int tt = e >> 5, dd = e & 31;
        tile[tt][dd] = V[((size_t)b * Tn + t0 + tt) * Dn + d0 + dd];
    }
    __syncthreads();
#pragma unroll
    for (int i = 0; i < 4; ++i) {
        int e = tid + i * 256;
        int dd = e >> 5, tt = e & 31;
        g_vt[((size_t)b * Dn + d0 + dd) * Tn + t0 + perm8(tt)] = f2tf(tile[tt][dd]);
    }
}

// ---------------------------------------------------------------------------
// MEGA: grid 1184.
//  bid [0,96):     scores tiles (lower-tri, 128x256), K=8192 -> g_sc
//  bid [96,160):   out_a = QR @ state (128x256), K=8192      -> g_oa
//  bid [160,1184): new_state (128x256), K=512                -> outns
// ---------------------------------------------------------------------------
__global__ void __launch_bounds__(NT, 1) mega_gemm(const float* __restrict__ state,
                                                   float* __restrict__ outns) {
    extern __shared__ uint32_t smu[];
    uint32_t sb = smem_u32(smu);

    const int bid = blockIdx.x;
    const int lane = threadIdx.x & 31, wid = threadIdx.x >> 5;
    const int gid = lane >> 2, tig = lane & 3;
    const int wm = (wid & 1) * 64, wn = (wid >> 1) * 64;

    float c[32][4] = {};

    if (bid < 96) {
        // ---- scores ----
        constexpr int TRI_T[6] = {0, 1, 2, 2, 3, 3};
        constexpr int TRI_S[6] = {0, 0, 0, 1, 0, 1};
        const int bh = bid & 15, q = bid >> 4;
        const int t0 = TRI_T[q] * BM, s0 = TRI_S[q] * BN;
        const float* Asrc = g_qr + ((size_t)bh * Tn + t0) * Nn;
        const float* Bsrc = g_qr + ((size_t)bh * Tn + s0) * Nn;

        gemm_main(sb, smu, Nn / BK,
                  [&](int kt) { return SrcPair{Asrc + kt * BK, Nn, Bsrc + kt * BK, Nn}; },
                  wm, wn, gid, tig, c);

        // epilogue: mask on true s; store column at perm8(s) (s is the
        // contraction index of the downstream outb GEMM).
        float* Sc = g_sc + (size_t)bh * Tn * Tn;
#pragma unroll
        for (int im = 0; im < 4; ++im)
#pragma unroll
            for (int jn = 0; jn < 8; ++jn) {
                int t = t0 + wm + im * 16 + gid;
                int s = s0 + wn + jn * 8 + tig * 2;
                float* cc = c[im * 8 + jn];
                Sc[(size_t)t * Tn + perm8(s)]           = (s     < t) ? f2tf(cc[0] * SCALEF) : 0.f;
                Sc[(size_t)t * Tn + perm8(s + 1)]       = (s + 1 < t) ? f2tf(cc[1] * SCALEF) : 0.f;
                Sc[(size_t)(t + 8) * Tn + perm8(s)]     = (s     < t + 8) ? f2tf(cc[2] * SCALEF) : 0.f;
                Sc[(size_t)(t + 8) * Tn + perm8(s + 1)] = (s + 1 < t + 8) ? f2tf(cc[3] * SCALEF) : 0.f;
            }
    } else if (bid < 160) {
        // ---- out_a = QR @ state (d covers full 256) ----
        const int r = bid - 96;
        const int tb = r & 3, bh = r >> 2;
        const int t0 = tb * BM;
        const float* Asrc = g_qr + ((size_t)bh * Tn + t0) * Nn;
        const float* Bsrc = g_st + (size_t)bh * Dn * Nn;

        gemm_main(sb, smu, Nn / BK,
                  [&](int kt) { return SrcPair{Asrc + kt * BK, Nn, Bsrc + kt * BK, Nn}; },
                  wm, wn, gid, tig, c);

        float* O = g_oa + ((size_t)bh * Tn + t0) * Dn;
#pragma unroll
        for (int im = 0; im < 4; ++im)
#pragma unroll
            for (int jn = 0; jn < 8; ++jn) {
                int rr = wm + im * 16 + gid;
                int cN = wn + jn * 8 + tig * 2;
                float* cc = c[im * 8 + jn];
                O[(size_t)rr * Dn + cN]           = cc[0];
                O[(size_t)rr * Dn + cN + 1]       = cc[1];
                O[(size_t)(rr + 8) * Dn + cN]     = cc[2];
                O[(size_t)(rr + 8) * Dn + cN + 1] = cc[3];
            }
    } else {
        // ---- new_state ----
        const int r = bid - 160;
        const int nb = r & 63, bh = r >> 6, b = bh >> 2;
        const int n0 = nb * BM;
        const float* Asrc = g_qt + ((size_t)bh * Nn + n0) * Tn;
        const float* Bsrc = g_vt + (size_t)b * Dn * Tn;

        gemm_main(sb, smu, Tn / BK,
                  [&](int kt) { return SrcPair{Asrc + kt * BK, Tn, Bsrc + kt * BK, Tn}; },
                  wm, wn, gid, tig, c);

        const float* St = state + ((size_t)bh * Nn + n0) * Dn;
        float* O = outns + ((size_t)bh * Nn + n0) * Dn;
#pragma unroll
        for (int im = 0; im < 4; ++im)
#pragma unroll
            for (int jn = 0; jn < 8; ++jn) {
                int rr = wm + im * 16 + gid;
                int cN = wn + jn * 8 + tig * 2;
                float* cc = c[im * 8 + jn];
                O[(size_t)rr * Dn + cN]           = St[(size_t)rr * Dn + cN]           + SCALEF * cc[0];
                O[(size_t)rr * Dn + cN + 1]       = St[(size_t)rr * Dn + cN + 1]       + SCALEF * cc[1];
                O[(size_t)(rr + 8) * Dn + cN]     = St[(size_t)(rr + 8) * Dn + cN]     + SCALEF * cc[2];
                O[(size_t)(rr + 8) * Dn + cN + 1] = St[(size_t)(rr + 8) * Dn + cN + 1] + SCALEF * cc[3];
            }
    }
}

// ---------------------------------------------------------------------------
// OUT_B: out = scores @ V + g_oa. grid 64 (tb 4 x bh 16), K = (tb+1)*128.
// ---------------------------------------------------------------------------
__global__ void __launch_bounds__(NT, 1) outb_gemm(float* __restrict__ out) {
    extern __shared__ uint32_t smu[];
    uint32_t sb = smem_u32(smu);

    const int bid = blockIdx.x;
    const int tb = bid & 3, bh = bid >> 2, b = bh >> 2;
    const int t0 = tb * BM;
    const int lane = threadIdx.x & 31, wid = threadIdx.x >> 5;
    const int gid = lane >> 2, tig = lane & 3;
    const int wm = (wid & 1) * 64, wn = (wid >> 1) * 64;

    const float* Asrc = g_sc + ((size_t)bh * Tn + t0) * Tn;
    const float* Bsrc = g_vt + (size_t)b * Dn * Tn;
    const int KT = (tb + 1) * (BM / BK);

    float c[32][4] = {};
    gemm_main(sb, smu, KT,
              [&](int kt) { return SrcPair{Asrc + kt * BK, Tn, Bsrc + kt * BK, Tn}; },
              wm, wn, gid, tig, c);

    const float* P = g_oa + ((size_t)bh * Tn + t0) * Dn;
    float* O = out + ((size_t)bh * Tn + t0) * Dn;
#pragma unroll
    for (int im = 0; im < 4; ++im)
#pragma unroll
        for (int jn = 0; jn < 8; ++jn) {
            int rr = wm + im * 16 + gid;
            int cN = wn + jn * 8 + tig * 2;
            float* cc = c[im * 8 + jn];
            O[(size_t)rr * Dn + cN]           = cc[0] + P[(size_t)rr * Dn + cN];
            O[(size_t)rr * Dn + cN + 1]       = cc[1] + P[(size_t)rr * Dn + cN + 1];
            O[(size_t)(rr + 8) * Dn + cN]     = cc[2] + P[(size_t)(rr + 8) * Dn + cN];
            O[(size_t)(rr + 8) * Dn + cN + 1] = cc[3] + P[(size_t)(rr + 8) * Dn + cN + 1];
        }
}

}  // namespace

extern "C" void kernel_launch(void* const* d_in, const int* in_sizes, int n_in,
                              void* d_out, int out_size) {
    const float* Q     = (const float*)d_in[0];
    const float* V     = (const float*)d_in[1];
    const float* state = (const float*)d_in[2];
    const float* cosb  = (const float*)d_in[3];
    const float* sinb  = (const float*)d_in[4];
    float* out = (float*)d_out;

    cudaFuncSetAttribute(mega_gemm, cudaFuncAttributeMaxDynamicSharedMemorySize, SMEM_TOTAL);
    cudaFuncSetAttribute(outb_gemm, cudaFuncAttributeMaxDynamicSharedMemorySize, SMEM_TOTAL);

    rope_kernel<<<dim3(Nn / 64, Tn / 32, BHn), 256>>>(Q, cosb, sinb);
    stateT_kernel<<<dim3(Nn / 32, Dn / 32, BHn), 256>>>(state);
    vT_kernel<<<dim3(Tn / 32, Dn / 32, Bz), 256>>>(V);

    mega_gemm<<<1184, NT, SMEM_TOTAL>>>(state, out + (size_t)BHn * Tn * Dn);
    outb_gemm<<<64, NT, SMEM_TOTAL>>>(out);
}